// round 2
// baseline (speedup 1.0000x reference)
#include <cuda_runtime.h>
#include <math.h>

#define B 64
#define H 2048
#define D 512
#define HID 512
#define M_TOTAL (B*H)
#define MASK_FILL_F (-4294967295.0f)

#define BM 128
#define BN 128
#define BK 16
#define TM 8
#define TN 8
#define HCHUNK 256

// Scratch (no allocations allowed in kernel_launch)
__device__ float g_gate[B*D];     // diag(W) * K
__device__ float g_score[B*H];    // scores, then alpha (in place)
__device__ int   g_mask_mode;     // 0=uint8, 1=int32, 2=float32

// ---------------------------------------------------------------------------
// Kernel D: classify mask dtype from its byte pattern (single block).
//   int32 0/1  -> nonzero bytes only at i%4==0, all values <=1
//   uint8 0/1  -> nonzero bytes at arbitrary offsets, values <=1
//   float 1.0f -> bytes 0x80/0x3F present (value > 1)
// ---------------------------------------------------------------------------
__global__ void k_detect_mask(const unsigned char* __restrict__ m) {
    __shared__ int s_gt1, s_other;
    if (threadIdx.x == 0) { s_gt1 = 0; s_other = 0; }
    __syncthreads();
    int lgt1 = 0, lother = 0;
    for (int i = threadIdx.x; i < B*H; i += blockDim.x) {
        unsigned char v = m[i];
        if (v > 1) lgt1 = 1;
        if (v != 0 && (i & 3) != 0) lother = 1;
    }
    if (lgt1)   atomicOr(&s_gt1, 1);
    if (lother) atomicOr(&s_other, 1);
    __syncthreads();
    if (threadIdx.x == 0)
        g_mask_mode = s_gt1 ? 2 : (s_other ? 0 : 1);
}

// ---------------------------------------------------------------------------
// Kernel 0: gate precompute + zero score buffer + zero output
// ---------------------------------------------------------------------------
__global__ void k_prep(const float* __restrict__ Kmat,
                       const float* __restrict__ W,
                       float* __restrict__ out) {
    int i = blockIdx.x * blockDim.x + threadIdx.x;   // 0 .. B*H-1
    if (i < B*D) {
        int k = i % D;
        g_gate[i] = W[k*D + k] * Kmat[i];
        out[i] = 0.0f;
    }
    if (i < B*H) g_score[i] = 0.0f;
}

// ---------------------------------------------------------------------------
// Kernel 1: fused GEMM + relu + w2-reduction -> partial scores (atomicAdd)
//   X[m,k] = V[m,k] * g[b(m),k]   (g folded into the w1 tile load)
//   score[m] += sum_n relu( (X @ w1)[m,n] + b1[n] ) * w2[n]   over this N-tile
// 128x128x512 tile, 256 threads, 8x8 microtile, fma.rn.f32x2 accumulators.
// ---------------------------------------------------------------------------
__global__ __launch_bounds__(256) void k_gemm_score(
        const float* __restrict__ V,
        const float* __restrict__ w1,
        const float* __restrict__ b1,
        const float* __restrict__ w2) {
    __shared__ float Xs[BM][BK + 4];      // [m][k], padded stride 20
    __shared__ float Ws[BK][BN];          // [k][n], gate pre-multiplied
    __shared__ float gsh[D];
    __shared__ float red[BM][17];

    const int tid = threadIdx.x;
    const int tx  = tid & 15;
    const int ty  = tid >> 4;
    const int row0 = blockIdx.x * BM;     // 1024 M-tiles; each inside one batch
    const int b    = row0 / H;
    const int n0   = blockIdx.y * BN;     // 4 N-tiles

    for (int i = tid; i < D; i += 256) gsh[i] = g_gate[b*D + i];
    __syncthreads();

    unsigned long long acc[TM][TN/2];
    #pragma unroll
    for (int i = 0; i < TM; i++)
        #pragma unroll
        for (int q = 0; q < TN/2; q++) acc[i][q] = 0ULL;

    const float* Vblk = V + (long long)row0 * D;

    for (int kk = 0; kk < D; kk += BK) {
        // X tile: 128x16 (2 float4 per thread), natural [m][k] layout
        #pragma unroll
        for (int l = 0; l < 2; l++) {
            int lin = tid + l*256;
            int m   = lin >> 2;
            int k4  = (lin & 3) << 2;
            float4 v = *reinterpret_cast<const float4*>(&Vblk[(long long)m*D + kk + k4]);
            Xs[m][k4+0] = v.x; Xs[m][k4+1] = v.y;
            Xs[m][k4+2] = v.z; Xs[m][k4+3] = v.w;
        }
        // W tile: 16x128, gate folded in (X@w1 == V@(diag(g)@w1))
        #pragma unroll
        for (int l = 0; l < 2; l++) {
            int lin = tid + l*256;
            int k   = lin >> 5;
            int n4  = (lin & 31) << 2;
            float gk = gsh[kk + k];
            float4 w = *reinterpret_cast<const float4*>(&w1[(long long)(kk+k)*HID + n0 + n4]);
            Ws[k][n4+0] = w.x*gk; Ws[k][n4+1] = w.y*gk;
            Ws[k][n4+2] = w.z*gk; Ws[k][n4+3] = w.w*gk;
        }
        __syncthreads();

        #pragma unroll
        for (int k = 0; k < BK; k++) {
            unsigned long long bvec[TN/2];
            const unsigned long long* wr =
                reinterpret_cast<const unsigned long long*>(&Ws[k][tx*TN]);
            #pragma unroll
            for (int q = 0; q < TN/2; q++) bvec[q] = wr[q];
            #pragma unroll
            for (int i = 0; i < TM; i++) {
                float a = Xs[ty*TM + i][k];          // broadcast across tx
                unsigned long long a2;
                asm("mov.b64 %0, {%1, %1};" : "=l"(a2) : "f"(a));
                #pragma unroll
                for (int q = 0; q < TN/2; q++)
                    asm("fma.rn.f32x2 %0, %1, %2, %0;"
                        : "+l"(acc[i][q]) : "l"(a2), "l"(bvec[q]));
            }
        }
        __syncthreads();
    }

    // Epilogue: relu + dot with w2 over this thread's 8 columns
    float b1v[TN], w2v[TN];
    #pragma unroll
    for (int j = 0; j < TN; j++) {
        b1v[j] = b1[n0 + tx*TN + j];
        w2v[j] = w2[n0 + tx*TN + j];
    }
    #pragma unroll
    for (int i = 0; i < TM; i++) {
        float s = 0.0f;
        #pragma unroll
        for (int q = 0; q < TN/2; q++) {
            float2 v = *reinterpret_cast<float2*>(&acc[i][q]);
            float c0 = v.x + b1v[q*2+0];
            float c1 = v.y + b1v[q*2+1];
            s += fmaxf(c0, 0.0f) * w2v[q*2+0] + fmaxf(c1, 0.0f) * w2v[q*2+1];
        }
        red[ty*TM + i][tx] = s;
    }
    __syncthreads();
    if (tid < BM) {
        float s = 0.0f;
        #pragma unroll
        for (int t = 0; t < 16; t++) s += red[tid][t];
        atomicAdd(&g_score[row0 + tid], s);
    }
}

// ---------------------------------------------------------------------------
// Kernel 2: masked softmax over h per batch, alpha stored in place
// ---------------------------------------------------------------------------
__global__ __launch_bounds__(256) void k_softmax(const void* __restrict__ mask_raw) {
    const int b   = blockIdx.x;
    const int tid = threadIdx.x;
    __shared__ float sh[256];

    const int mode = g_mask_mode;
    const unsigned char* m8  = (const unsigned char*)mask_raw;
    const int*           m32 = (const int*)mask_raw;
    const float*         mf  = (const float*)mask_raw;

    float s[8];
    float mx = -3.0e38f;
    #pragma unroll
    for (int l = 0; l < 8; l++) {
        int h = tid + l*256;
        int idx = b*H + h;
        bool masked;
        if (mode == 1)      masked = (m32[idx] != 0);
        else if (mode == 2) masked = (mf[idx] != 0.0f);
        else                masked = (m8[idx] != 0);
        float v = g_score[idx];
        if (masked) v = MASK_FILL_F;
        s[l] = v;
        mx = fmaxf(mx, v);
    }
    sh[tid] = mx; __syncthreads();
    for (int off = 128; off > 0; off >>= 1) {
        if (tid < off) sh[tid] = fmaxf(sh[tid], sh[tid + off]);
        __syncthreads();
    }
    mx = sh[0];
    __syncthreads();

    float e[8];
    float sum = 0.0f;
    #pragma unroll
    for (int l = 0; l < 8; l++) { e[l] = expf(s[l] - mx); sum += e[l]; }
    sh[tid] = sum; __syncthreads();
    for (int off = 128; off > 0; off >>= 1) {
        if (tid < off) sh[tid] += sh[tid + off];
        __syncthreads();
    }
    float inv = 1.0f / sh[0];
    #pragma unroll
    for (int l = 0; l < 8; l++) g_score[b*H + tid + l*256] = e[l] * inv;
}

// ---------------------------------------------------------------------------
// Kernel 3: attn[b,d] = sum_h alpha[b,h] * V[b,h,d]   (h split over grid.y)
// ---------------------------------------------------------------------------
__global__ __launch_bounds__(256) void k_wsum(const float* __restrict__ V,
                                              float* __restrict__ out) {
    const int b   = blockIdx.x;
    const int h0  = blockIdx.y * HCHUNK;
    const int tid = threadIdx.x;
    __shared__ float al[HCHUNK];
    al[tid] = g_score[b*H + h0 + tid];
    __syncthreads();

    const float* Vb = V + ((long long)b*H + h0) * D;
    float a0 = 0.0f, a1 = 0.0f;
    #pragma unroll 4
    for (int h = 0; h < HCHUNK; h++) {
        float w = al[h];
        a0 = fmaf(w, Vb[(long long)h*D + tid],        a0);
        a1 = fmaf(w, Vb[(long long)h*D + tid + 256],  a1);
    }
    atomicAdd(&out[b*D + tid],       a0);
    atomicAdd(&out[b*D + tid + 256], a1);
}

// ---------------------------------------------------------------------------
extern "C" void kernel_launch(void* const* d_in, const int* in_sizes, int n_in,
                              void* d_out, int out_size) {
    const float* Kmat = (const float*)d_in[0];
    const float* V    = (const float*)d_in[1];
    const void*  mask = d_in[2];
    const float* W    = (const float*)d_in[3];
    const float* w1   = (const float*)d_in[4];
    const float* b1   = (const float*)d_in[5];
    const float* w2   = (const float*)d_in[6];
    // b2 (d_in[7]) is a constant shift of all scores -> softmax-invariant, unused.
    float* out = (float*)d_out;

    k_detect_mask<<<1, 1024>>>((const unsigned char*)mask);

    k_prep<<<(M_TOTAL + 255)/256, 256>>>(Kmat, W, out);

    dim3 ggrid(M_TOTAL / BM, HID / BN);           // 1024 x 4
    k_gemm_score<<<ggrid, 256>>>(V, w1, b1, w2);

    k_softmax<<<B, 256>>>(mask);

    k_wsum<<<dim3(B, H / HCHUNK), 256>>>(V, out); // 64 x 8
}

// round 4
// speedup vs baseline: 6.7884x; 6.7884x over previous
#include <cuda_runtime.h>
#include <math.h>
#include <cstdint>

#define B 64
#define H 2048
#define D 512
#define HID 512
#define M_TOTAL (B*H)
#define MASK_FILL_F (-4294967295.0f)
#define HCHUNK 256

// Arch feature gate: tcgen05/TMEM only exist in the sm_103a/sm_100a passes.
#if defined(__CUDA_ARCH_FEAT_SM103_ALL) || defined(__CUDA_ARCH_FEAT_SM100_ALL) || defined(__CUDA_ARCH_FEAT_SM101_ALL)
#define TC_OK 1
#else
#define TC_OK 0
#endif

// ---------------------------------------------------------------------------
// PTX helpers (guarded — only emitted in the *_a pass)
// ---------------------------------------------------------------------------
#if TC_OK
__device__ __forceinline__ uint32_t smem_to_u32(const void* p) {
    uint32_t a;
    asm("{ .reg .u64 t; cvta.to.shared.u64 t, %1; cvt.u32.u64 %0, t; }"
        : "=r"(a) : "l"(p));
    return a;
}
__device__ __forceinline__ uint32_t elect_one_pred() {
    uint32_t pred;
    asm volatile("{\n\t.reg .pred p;\n\telect.sync _|p, 0xFFFFFFFF;\n\t"
                 "selp.b32 %0, 1, 0, p;\n\t}" : "=r"(pred));
    return pred;
}
#define TCGEN05_ALLOC(sa, n) \
    asm volatile("tcgen05.alloc.cta_group::1.sync.aligned.shared::cta.b32 [%0], %1;" \
                 :: "r"((uint32_t)(sa)), "r"((uint32_t)(n)) : "memory")
#define TCGEN05_DEALLOC(ta, n) \
    asm volatile("tcgen05.dealloc.cta_group::1.sync.aligned.b32 %0, %1;" :: "r"(ta), "r"((uint32_t)(n)))
#define TCGEN05_RELINQUISH() \
    asm volatile("tcgen05.relinquish_alloc_permit.cta_group::1.sync.aligned;")
#define TCGEN05_COMMIT(mb) \
    asm volatile("tcgen05.commit.cta_group::1.mbarrier::arrive::one.shared::cluster.b64 [%0];" \
                 :: "r"((uint32_t)(mb)) : "memory")
#define TCGEN05_WAIT_LD()  asm volatile("tcgen05.wait::ld.sync.aligned;" ::: "memory")
#define TCGEN05_FENCE_BEFORE() asm volatile("tcgen05.fence::before_thread_sync;" ::: "memory")
#define TCGEN05_FENCE_AFTER()  asm volatile("tcgen05.fence::after_thread_sync;" ::: "memory")
#define FENCE_ASYNC_SHARED() asm volatile("fence.proxy.async.shared::cta;" ::: "memory")
#define MBARRIER_INIT(mb, cnt) \
    asm volatile("mbarrier.init.shared.b64 [%0], %1;" :: "r"((uint32_t)(mb)), "r"((uint32_t)(cnt)) : "memory")
#define MBARRIER_WAIT_PARITY(mb, ph) do { \
    uint32_t _mb = (uint32_t)(mb); uint32_t _ph = (uint32_t)(ph); uint32_t _done; \
    asm volatile("{\n\t.reg .pred p;\n\t" \
        "mbarrier.try_wait.parity.acquire.cta.shared::cta.b64 p, [%1], %2;\n\t" \
        "selp.b32 %0, 1, 0, p;\n\t}" : "=r"(_done) : "r"(_mb), "r"(_ph) : "memory"); \
    if (!_done) { \
        asm volatile("{\n\t.reg .pred P1;\n\t" \
            "WL_%=:\n\t" \
            "mbarrier.try_wait.parity.acquire.cta.shared::cta.b64 P1, [%0], %1, 0x989680;\n\t" \
            "@P1 bra.uni WD_%=;\n\t" \
            "bra.uni WL_%=;\n\t" \
            "WD_%=:\n\t}" :: "r"(_mb), "r"(_ph) : "memory"); \
    } } while (0)
#define TCGEN05_LD_32X32B_X32(r, ta) \
    asm volatile("tcgen05.ld.sync.aligned.32x32b.x32.b32 " \
        "{%0, %1, %2, %3, %4, %5, %6, %7, %8, %9, %10, %11, %12, %13, %14, %15, " \
        " %16, %17, %18, %19, %20, %21, %22, %23, %24, %25, %26, %27, %28, %29, %30, %31}, [%32];" \
        : "=r"((r)[0]),  "=r"((r)[1]),  "=r"((r)[2]),  "=r"((r)[3]), \
          "=r"((r)[4]),  "=r"((r)[5]),  "=r"((r)[6]),  "=r"((r)[7]), \
          "=r"((r)[8]),  "=r"((r)[9]),  "=r"((r)[10]), "=r"((r)[11]), \
          "=r"((r)[12]), "=r"((r)[13]), "=r"((r)[14]), "=r"((r)[15]), \
          "=r"((r)[16]), "=r"((r)[17]), "=r"((r)[18]), "=r"((r)[19]), \
          "=r"((r)[20]), "=r"((r)[21]), "=r"((r)[22]), "=r"((r)[23]), \
          "=r"((r)[24]), "=r"((r)[25]), "=r"((r)[26]), "=r"((r)[27]), \
          "=r"((r)[28]), "=r"((r)[29]), "=r"((r)[30]), "=r"((r)[31]) \
        : "r"(ta))

static constexpr uint64_t SMEM_DESC_BASE_SW128 =
    (uint64_t(2)  << 61) | (uint64_t(1) << 46) | (uint64_t(64) << 32) | (uint64_t(1) << 16);
#define MAKE_SMEM_DESC(a) (SMEM_DESC_BASE_SW128 | ((uint64_t)((a) >> 4) & 0x3FFF))

// idesc kind::tf32: dtype=F32(1)@[4], atype=TF32(2)@[7:9], btype=TF32(2)@[10:12],
// N/8 @[17:23), M/16 @[24:29)
static constexpr uint32_t IDESC_TF32 =
    (1u << 4) | (2u << 7) | (2u << 10) | ((256u / 8) << 17) | ((128u / 16) << 24);

__device__ __forceinline__ void mma_tf32_ss(uint32_t d, uint64_t ad, uint64_t bd,
                                            uint32_t idesc, unsigned en) {
    asm volatile("{\n\t.reg .pred p;\n\tsetp.ne.u32 p, %5, 0;\n\t"
        "tcgen05.mma.cta_group::1.kind::tf32 [%0], %1, %2, %3, {%4, %4, %4, %4}, p;\n\t}"
        :: "r"(d), "l"(ad), "l"(bd), "r"(idesc), "r"(0u), "r"(en) : "memory");
}
#endif // TC_OK

#define SW128(o) ((o) ^ (((o) >> 3) & 0x70))

// ---------------------------------------------------------------------------
// Scratch
// ---------------------------------------------------------------------------
__device__ float    g_gate[B*D];          // diag(W) * K
__device__ float    g_score[B*H];         // scores -> alpha (in place)
__device__ uint32_t g_w1t[HID*D];         // w1^T in tf32 (n-major: [n][k])
__device__ int      g_flag_gt1, g_flag_other;

// ---------------------------------------------------------------------------
// Kernel 0: gate + zero output + zero detect flags
// ---------------------------------------------------------------------------
__global__ void k_prep(const float* __restrict__ Kmat,
                       const float* __restrict__ W,
                       float* __restrict__ out) {
    int i = blockIdx.x * blockDim.x + threadIdx.x;
    if (i == 0) { g_flag_gt1 = 0; g_flag_other = 0; }
    if (i < B*D) {
        int k = i % D;
        g_gate[i] = W[k*D + k] * Kmat[i];
        out[i] = 0.0f;
    }
}

// ---------------------------------------------------------------------------
// Kernel D: classify mask dtype from byte pattern
// ---------------------------------------------------------------------------
__global__ void k_detect_mask(const unsigned char* __restrict__ m) {
    int lgt1 = 0, lother = 0;
    int base = blockIdx.x * 2048;
    for (int j = threadIdx.x; j < 2048; j += 256) {
        int i = base + j;
        unsigned char v = m[i];
        if (v > 1) lgt1 = 1;
        if (v != 0 && (i & 3) != 0) lother = 1;
    }
    if (__syncthreads_or(lgt1))   { if (threadIdx.x == 0) atomicOr(&g_flag_gt1, 1); }
    if (__syncthreads_or(lother)) { if (threadIdx.x == 0) atomicOr(&g_flag_other, 1); }
}

// ---------------------------------------------------------------------------
// Kernel C: w1 [k][n] -> g_w1t [n][k] in tf32 (rna). Only used by TC path,
// but compiled everywhere (cvt.rna.tf32 is plain compute_90+ PTX? use manual
// rounding to stay arch-portable).
// ---------------------------------------------------------------------------
__device__ __forceinline__ uint32_t to_tf32(float f) {
#if TC_OK
    uint32_t u;
    asm("cvt.rna.tf32.f32 %0, %1;" : "=r"(u) : "f"(f));
    return u;
#else
    // round-to-nearest-even into 19-bit mantissa-truncated fp32 (unused path)
    uint32_t x = __float_as_uint(f);
    x += 0x1000u + ((x >> 13) & 1u);
    return x & 0xFFFFE000u;
#endif
}

__global__ void k_cvt_w1(const float* __restrict__ w1) {
    __shared__ float t[32][33];
    int x = threadIdx.x, y = threadIdx.y;           // 32 x 8
    int kn0 = blockIdx.y * 32;
    int nn0 = blockIdx.x * 32;
    #pragma unroll
    for (int r = 0; r < 32; r += 8)
        t[y + r][x] = w1[(kn0 + y + r) * HID + nn0 + x];
    __syncthreads();
    #pragma unroll
    for (int r = 0; r < 32; r += 8)
        g_w1t[(nn0 + y + r) * D + kn0 + x] = to_tf32(t[x][y + r]);
}

// ---------------------------------------------------------------------------
// Kernel 1: GEMM + fused relu/w2 epilogue -> g_score
//   TC path  : tcgen05 tf32, M=128/CTA, N=512 in TMEM, K in 16 chunks of 32.
//   Fallback : f32x2 SGEMM, same CTA->rows mapping, N looped in 4 chunks.
// ---------------------------------------------------------------------------
#define OFF_TMEM 0
#define OFF_BIAS 128          // 512 f32
#define OFF_W2V  2176         // 512 f32
#define OFF_GATE 4224         // 512 f32
#define OFF_A(buf) (8192 + (buf)*16384)     // 2 x 16 KB
#define OFF_BT(buf) (40960 + (buf)*65536)   // 2 x 64 KB
#define SMEM_BYTES (40960 + 2*65536)        // 172032

__global__ __launch_bounds__(256, 1) void k_gemm_tc(
        const float* __restrict__ V,
        const float* __restrict__ w1,
        const float* __restrict__ b1,
        const float* __restrict__ w2) {
    extern __shared__ char smem[];
    const int tid = threadIdx.x;
    const int row0 = blockIdx.x * 128;
    const int b = row0 >> 11;              // row0 / H

#if TC_OK
    // ======================= tcgen05 tf32 path =======================
    const uint32_t sb = smem_to_u32(smem);
    const int wid = tid >> 5;
    const int lid = tid & 31;

    float* bias = (float*)(smem + OFF_BIAS);
    float* w2s  = (float*)(smem + OFF_W2V);
    float* gs   = (float*)(smem + OFF_GATE);
    for (int i = tid; i < D; i += 256) {
        bias[i] = b1[i];
        w2s[i]  = w2[i];
        gs[i]   = g_gate[b*D + i];
    }
    if (wid == 0) TCGEN05_ALLOC(sb + OFF_TMEM, 512);
    if (tid == 0) { MBARRIER_INIT(sb + 8, 1); MBARRIER_INIT(sb + 16, 1); }
    __syncthreads();
    uint32_t tmem;
    asm volatile("ld.shared.b32 %0, [%1];" : "=r"(tmem) : "r"(sb + OFF_TMEM));

    const float* Vblk = V + (long long)row0 * D;
    int par[2] = {0, 0};

    for (int i = 0; i < 16; i++) {
        const int buf = i & 1;
        if (i >= 2) {
            MBARRIER_WAIT_PARITY(sb + 8 + buf*8, par[buf]);
            par[buf] ^= 1;
        }
        const int kk = i * 32;
        // A tile: 128 rows x 32 tf32 (V * gate), SW128
        #pragma unroll
        for (int l = 0; l < 4; l++) {
            int lin = tid + l*256;
            int m   = lin >> 3;
            int kq  = lin & 7;
            float4 v = *reinterpret_cast<const float4*>(
                           Vblk + (long long)m*D + kk + kq*4);
            const float* gp = gs + kk + kq*4;
            uint4 t;
            t.x = to_tf32(v.x * gp[0]); t.y = to_tf32(v.y * gp[1]);
            t.z = to_tf32(v.z * gp[2]); t.w = to_tf32(v.w * gp[3]);
            uint32_t off = (uint32_t)(m*128 + kq*16);
            *reinterpret_cast<uint4*>(smem + OFF_A(buf) + SW128(off)) = t;
        }
        // B tile: 512 n-rows x 32 tf32, from g_w1t, SW128
        #pragma unroll
        for (int l = 0; l < 16; l++) {
            int lin = tid + l*256;
            int n   = lin >> 3;
            int kq  = lin & 7;
            uint4 w = *reinterpret_cast<const uint4*>(g_w1t + n*D + kk + kq*4);
            uint32_t off = (uint32_t)(n*128 + kq*16);
            *reinterpret_cast<uint4*>(smem + OFF_BT(buf) + SW128(off)) = w;
        }
        FENCE_ASYNC_SHARED();
        __syncthreads();

        if (wid == 0 && elect_one_pred()) {
            uint64_t ad = MAKE_SMEM_DESC(sb + OFF_A(buf));
            uint64_t bd = MAKE_SMEM_DESC(sb + OFF_BT(buf));
            #pragma unroll
            for (int ks = 0; ks < 4; ks++) {
                unsigned en = (i > 0 || ks > 0) ? 1u : 0u;
                mma_tf32_ss(tmem,       ad + ks*2, bd + ks*2,        IDESC_TF32, en);
                mma_tf32_ss(tmem + 256, ad + ks*2, bd + 2048 + ks*2, IDESC_TF32, en);
            }
            TCGEN05_COMMIT(sb + 8 + buf*8);
        }
    }

    MBARRIER_WAIT_PARITY(sb + 8,  par[0]);
    MBARRIER_WAIT_PARITY(sb + 16, par[1]);
    TCGEN05_FENCE_AFTER();

    if (wid < 4) {
        float s = 0.0f;
        #pragma unroll 1
        for (int c = 0; c < HID; c += 32) {
            uint32_t r[32];
            TCGEN05_LD_32X32B_X32(r, tmem + c);
            TCGEN05_WAIT_LD();
            #pragma unroll
            for (int j = 0; j < 32; j++) {
                float v = __uint_as_float(r[j]) + bias[c + j];
                s += fmaxf(v, 0.0f) * w2s[c + j];
            }
        }
        TCGEN05_FENCE_BEFORE();
        g_score[row0 + wid*32 + lid] = s;
    }
    __syncthreads();
    if (wid == 0) {
        TCGEN05_RELINQUISH();
        TCGEN05_DEALLOC(tmem, 512);
    }
#else
    // ======================= f32x2 SGEMM fallback =======================
    // smem carve: Xs[128][20], Ws[16][128], gsh[512], red[128][17]
    float* Xs  = (float*)smem;                           // 10240 B
    float* Ws  = (float*)(smem + 128*20*4);              //  8192 B
    float* gsh = (float*)(smem + 128*20*4 + 16*128*4);   //  2048 B
    float* red = gsh + 512;                              //  8704 B
    const int tx = tid & 15;
    const int ty = tid >> 4;

    for (int i = tid; i < D; i += 256) gsh[i] = g_gate[b*D + i];
    __syncthreads();

    float scoreAcc[8];
    #pragma unroll
    for (int i = 0; i < 8; i++) scoreAcc[i] = 0.0f;

    const float* Vblk = V + (long long)row0 * D;

    for (int n0 = 0; n0 < HID; n0 += 128) {
        unsigned long long acc[8][4];
        #pragma unroll
        for (int i = 0; i < 8; i++)
            #pragma unroll
            for (int q = 0; q < 4; q++) acc[i][q] = 0ULL;

        for (int kk = 0; kk < D; kk += 16) {
            #pragma unroll
            for (int l = 0; l < 2; l++) {
                int lin = tid + l*256;
                int m   = lin >> 2;
                int k4  = (lin & 3) << 2;
                float4 v = *reinterpret_cast<const float4*>(
                               &Vblk[(long long)m*D + kk + k4]);
                Xs[m*20 + k4+0] = v.x; Xs[m*20 + k4+1] = v.y;
                Xs[m*20 + k4+2] = v.z; Xs[m*20 + k4+3] = v.w;
            }
            #pragma unroll
            for (int l = 0; l < 2; l++) {
                int lin = tid + l*256;
                int k   = lin >> 5;
                int n4  = (lin & 31) << 2;
                float gk = gsh[kk + k];
                float4 w = *reinterpret_cast<const float4*>(
                               &w1[(long long)(kk+k)*HID + n0 + n4]);
                Ws[k*128 + n4+0] = w.x*gk; Ws[k*128 + n4+1] = w.y*gk;
                Ws[k*128 + n4+2] = w.z*gk; Ws[k*128 + n4+3] = w.w*gk;
            }
            __syncthreads();

            #pragma unroll
            for (int k = 0; k < 16; k++) {
                unsigned long long bvec[4];
                const unsigned long long* wr =
                    reinterpret_cast<const unsigned long long*>(&Ws[k*128 + tx*8]);
                #pragma unroll
                for (int q = 0; q < 4; q++) bvec[q] = wr[q];
                #pragma unroll
                for (int i = 0; i < 8; i++) {
                    float a = Xs[(ty*8 + i)*20 + k];
                    unsigned long long a2;
                    asm("mov.b64 %0, {%1, %1};" : "=l"(a2) : "f"(a));
                    #pragma unroll
                    for (int q = 0; q < 4; q++)
                        asm("fma.rn.f32x2 %0, %1, %2, %0;"
                            : "+l"(acc[i][q]) : "l"(a2), "l"(bvec[q]));
                }
            }
            __syncthreads();
        }

        // relu + w2 partial dot for this n-chunk
        float b1v[8], w2v[8];
        #pragma unroll
        for (int j = 0; j < 8; j++) {
            b1v[j] = b1[n0 + tx*8 + j];
            w2v[j] = w2[n0 + tx*8 + j];
        }
        #pragma unroll
        for (int i = 0; i < 8; i++) {
            float s = 0.0f;
            #pragma unroll
            for (int q = 0; q < 4; q++) {
                float2 v = *reinterpret_cast<float2*>(&acc[i][q]);
                float c0 = v.x + b1v[q*2+0];
                float c1 = v.y + b1v[q*2+1];
                s += fmaxf(c0, 0.0f) * w2v[q*2+0] + fmaxf(c1, 0.0f) * w2v[q*2+1];
            }
            scoreAcc[i] += s;
        }
    }

    #pragma unroll
    for (int i = 0; i < 8; i++) red[(ty*8 + i)*17 + tx] = scoreAcc[i];
    __syncthreads();
    if (tid < 128) {
        float s = 0.0f;
        #pragma unroll
        for (int t = 0; t < 16; t++) s += red[tid*17 + t];
        g_score[row0 + tid] = s;
    }
#endif
}

// ---------------------------------------------------------------------------
// Kernel 2: masked softmax over h per batch, alpha stored in place
// ---------------------------------------------------------------------------
__global__ __launch_bounds__(256) void k_softmax(const void* __restrict__ mask_raw) {
    const int b   = blockIdx.x;
    const int tid = threadIdx.x;
    __shared__ float sh[256];

    const int mode = g_flag_gt1 ? 2 : (g_flag_other ? 0 : 1);
    const unsigned char* m8  = (const unsigned char*)mask_raw;
    const int*           m32 = (const int*)mask_raw;
    const float*         mf  = (const float*)mask_raw;

    float s[8];
    float mx = -3.0e38f;
    #pragma unroll
    for (int l = 0; l < 8; l++) {
        int idx = b*H + tid + l*256;
        bool masked;
        if (mode == 1)      masked = (m32[idx] != 0);
        else if (mode == 2) masked = (mf[idx] != 0.0f);
        else                masked = (m8[idx] != 0);
        float v = g_score[idx];
        if (masked) v = MASK_FILL_F;
        s[l] = v;
        mx = fmaxf(mx, v);
    }
    sh[tid] = mx; __syncthreads();
    for (int off = 128; off > 0; off >>= 1) {
        if (tid < off) sh[tid] = fmaxf(sh[tid], sh[tid + off]);
        __syncthreads();
    }
    mx = sh[0];
    __syncthreads();

    float e[8], sum = 0.0f;
    #pragma unroll
    for (int l = 0; l < 8; l++) { e[l] = expf(s[l] - mx); sum += e[l]; }
    sh[tid] = sum; __syncthreads();
    for (int off = 128; off > 0; off >>= 1) {
        if (tid < off) sh[tid] += sh[tid + off];
        __syncthreads();
    }
    float inv = 1.0f / sh[0];
    #pragma unroll
    for (int l = 0; l < 8; l++) g_score[b*H + tid + l*256] = e[l] * inv;
}

// ---------------------------------------------------------------------------
// Kernel 3: attn[b,d] = sum_h alpha[b,h] * V[b,h,d]
// ---------------------------------------------------------------------------
__global__ __launch_bounds__(256) void k_wsum(const float* __restrict__ V,
                                              float* __restrict__ out) {
    const int b   = blockIdx.x;
    const int h0  = blockIdx.y * HCHUNK;
    const int tid = threadIdx.x;
    __shared__ float al[HCHUNK];
    al[tid] = g_score[b*H + h0 + tid];
    __syncthreads();

    const float* Vb = V + ((long long)b*H + h0) * D;
    float a0 = 0.0f, a1 = 0.0f;
    #pragma unroll 4
    for (int h = 0; h < HCHUNK; h++) {
        float w = al[h];
        a0 = fmaf(w, Vb[(long long)h*D + tid],       a0);
        a1 = fmaf(w, Vb[(long long)h*D + tid + 256], a1);
    }
    atomicAdd(&out[b*D + tid],       a0);
    atomicAdd(&out[b*D + tid + 256], a1);
}

// ---------------------------------------------------------------------------
extern "C" void kernel_launch(void* const* d_in, const int* in_sizes, int n_in,
                              void* d_out, int out_size) {
    const float* Kmat = (const float*)d_in[0];
    const float* V    = (const float*)d_in[1];
    const void*  mask = d_in[2];
    const float* W    = (const float*)d_in[3];
    const float* w1   = (const float*)d_in[4];
    const float* b1   = (const float*)d_in[5];
    const float* w2   = (const float*)d_in[6];
    // b2 is a uniform score shift -> softmax-invariant, unused.
    float* out = (float*)d_out;

    cudaFuncSetAttribute(k_gemm_tc, cudaFuncAttributeMaxDynamicSharedMemorySize,
                         SMEM_BYTES);

    k_prep<<<(M_TOTAL + 255)/256, 256>>>(Kmat, W, out);
    k_detect_mask<<<64, 256>>>((const unsigned char*)mask);
    k_cvt_w1<<<dim3(16, 16), dim3(32, 8)>>>(w1);
    k_gemm_tc<<<M_TOTAL/128, 256, SMEM_BYTES>>>(V, w1, b1, w2);
    k_softmax<<<B, 256>>>(mask);
    k_wsum<<<dim3(B, H/HCHUNK), 256>>>(V, out);
}

// round 5
// speedup vs baseline: 9.9600x; 1.4672x over previous
#include <cuda_runtime.h>
#include <cuda_bf16.h>
#include <math.h>
#include <cstdint>

#define B 64
#define H 2048
#define D 512
#define HID 512
#define M_TOTAL (B*H)
#define MASK_FILL_F (-4294967295.0f)
#define HCHUNK 256

// Arch feature gate: tcgen05/TMEM only exist in the sm_103a/sm_100a passes.
#if defined(__CUDA_ARCH_FEAT_SM103_ALL) || defined(__CUDA_ARCH_FEAT_SM100_ALL) || defined(__CUDA_ARCH_FEAT_SM101_ALL)
#define TC_OK 1
#else
#define TC_OK 0
#endif

#define SW128(o) ((o) ^ (((o) >> 3) & 0x70))

// ---------------------------------------------------------------------------
// PTX helpers (guarded — only emitted in the *_a pass)
// ---------------------------------------------------------------------------
#if TC_OK
__device__ __forceinline__ uint32_t smem_to_u32(const void* p) {
    uint32_t a;
    asm("{ .reg .u64 t; cvta.to.shared.u64 t, %1; cvt.u32.u64 %0, t; }"
        : "=r"(a) : "l"(p));
    return a;
}
__device__ __forceinline__ uint32_t elect_one_pred() {
    uint32_t pred;
    asm volatile("{\n\t.reg .pred p;\n\telect.sync _|p, 0xFFFFFFFF;\n\t"
                 "selp.b32 %0, 1, 0, p;\n\t}" : "=r"(pred));
    return pred;
}
#define TCGEN05_ALLOC(sa, n) \
    asm volatile("tcgen05.alloc.cta_group::1.sync.aligned.shared::cta.b32 [%0], %1;" \
                 :: "r"((uint32_t)(sa)), "r"((uint32_t)(n)) : "memory")
#define TCGEN05_DEALLOC(ta, n) \
    asm volatile("tcgen05.dealloc.cta_group::1.sync.aligned.b32 %0, %1;" :: "r"(ta), "r"((uint32_t)(n)))
#define TCGEN05_RELINQUISH() \
    asm volatile("tcgen05.relinquish_alloc_permit.cta_group::1.sync.aligned;")
#define TCGEN05_COMMIT(mb) \
    asm volatile("tcgen05.commit.cta_group::1.mbarrier::arrive::one.shared::cluster.b64 [%0];" \
                 :: "r"((uint32_t)(mb)) : "memory")
#define TCGEN05_WAIT_LD()  asm volatile("tcgen05.wait::ld.sync.aligned;" ::: "memory")
#define TCGEN05_FENCE_BEFORE() asm volatile("tcgen05.fence::before_thread_sync;" ::: "memory")
#define TCGEN05_FENCE_AFTER()  asm volatile("tcgen05.fence::after_thread_sync;" ::: "memory")
#define FENCE_ASYNC_SHARED() asm volatile("fence.proxy.async.shared::cta;" ::: "memory")
#define MBARRIER_INIT(mb, cnt) \
    asm volatile("mbarrier.init.shared.b64 [%0], %1;" :: "r"((uint32_t)(mb)), "r"((uint32_t)(cnt)) : "memory")
#define MBARRIER_EXPECT_TX(mb, bytes) \
    asm volatile("mbarrier.arrive.expect_tx.shared.b64 _, [%0], %1;" \
                 :: "r"((uint32_t)(mb)), "r"((uint32_t)(bytes)) : "memory")
#define CP_ASYNC_BULK(dst, src, bytes, mb) \
    asm volatile("cp.async.bulk.shared::cta.global.mbarrier::complete_tx::bytes " \
                 "[%0], [%1], %2, [%3];" \
                 :: "r"((uint32_t)(dst)), "l"(src), "r"((uint32_t)(bytes)), \
                    "r"((uint32_t)(mb)) : "memory")
#define MBARRIER_WAIT_PARITY(mb, ph) do { \
    uint32_t _mb = (uint32_t)(mb); uint32_t _ph = (uint32_t)(ph); uint32_t _done; \
    asm volatile("{\n\t.reg .pred p;\n\t" \
        "mbarrier.try_wait.parity.acquire.cta.shared::cta.b64 p, [%1], %2;\n\t" \
        "selp.b32 %0, 1, 0, p;\n\t}" : "=r"(_done) : "r"(_mb), "r"(_ph) : "memory"); \
    if (!_done) { \
        asm volatile("{\n\t.reg .pred P1;\n\t" \
            "WL_%=:\n\t" \
            "mbarrier.try_wait.parity.acquire.cta.shared::cta.b64 P1, [%0], %1, 0x989680;\n\t" \
            "@P1 bra.uni WD_%=;\n\t" \
            "bra.uni WL_%=;\n\t" \
            "WD_%=:\n\t}" :: "r"(_mb), "r"(_ph) : "memory"); \
    } } while (0)
#define TCGEN05_LD_32X32B_X32(r, ta) \
    asm volatile("tcgen05.ld.sync.aligned.32x32b.x32.b32 " \
        "{%0, %1, %2, %3, %4, %5, %6, %7, %8, %9, %10, %11, %12, %13, %14, %15, " \
        " %16, %17, %18, %19, %20, %21, %22, %23, %24, %25, %26, %27, %28, %29, %30, %31}, [%32];" \
        : "=r"((r)[0]),  "=r"((r)[1]),  "=r"((r)[2]),  "=r"((r)[3]), \
          "=r"((r)[4]),  "=r"((r)[5]),  "=r"((r)[6]),  "=r"((r)[7]), \
          "=r"((r)[8]),  "=r"((r)[9]),  "=r"((r)[10]), "=r"((r)[11]), \
          "=r"((r)[12]), "=r"((r)[13]), "=r"((r)[14]), "=r"((r)[15]), \
          "=r"((r)[16]), "=r"((r)[17]), "=r"((r)[18]), "=r"((r)[19]), \
          "=r"((r)[20]), "=r"((r)[21]), "=r"((r)[22]), "=r"((r)[23]), \
          "=r"((r)[24]), "=r"((r)[25]), "=r"((r)[26]), "=r"((r)[27]), \
          "=r"((r)[28]), "=r"((r)[29]), "=r"((r)[30]), "=r"((r)[31]) \
        : "r"(ta))

static constexpr uint64_t SMEM_DESC_BASE_SW128 =
    (uint64_t(2)  << 61) | (uint64_t(1) << 46) | (uint64_t(64) << 32) | (uint64_t(1) << 16);
#define MAKE_SMEM_DESC(a) (SMEM_DESC_BASE_SW128 | ((uint64_t)((a) >> 4) & 0x3FFF))

// idesc kind::f16 (bf16 in, f32 accum): dtype=F32(1)@[4], atype=BF16(1)@[7],
// btype=BF16(1)@[10], N/8 @[17:23), M/16 @[24:29)   (N=256, M=128)
static constexpr uint32_t IDESC_BF16 =
    (1u << 4) | (1u << 7) | (1u << 10) | ((256u / 8) << 17) | ((128u / 16) << 24);

__device__ __forceinline__ void mma_bf16_ss(uint32_t d, uint64_t ad, uint64_t bd,
                                            uint32_t idesc, unsigned en) {
    asm volatile("{\n\t.reg .pred p;\n\tsetp.ne.u32 p, %5, 0;\n\t"
        "tcgen05.mma.cta_group::1.kind::f16 [%0], %1, %2, %3, {%4, %4, %4, %4}, p;\n\t}"
        :: "r"(d), "l"(ad), "l"(bd), "r"(idesc), "r"(0u), "r"(en) : "memory");
}
#endif // TC_OK

// ---------------------------------------------------------------------------
// Scratch
// ---------------------------------------------------------------------------
__device__ float    g_gate[B*D];          // diag(W) * K
__device__ float    g_score[B*H];         // scores -> alpha (in place)
// w1^T in bf16, stored as the exact SW128 SMEM image, per K-chunk of 64:
//   chunk c holds n=0..511 rows of 128 bytes (64 bf16, k = 64c..64c+63)
__device__ __align__(16) unsigned char g_w1s[8*65536];   // 512 KB
__device__ int      g_flag_gt1, g_flag_other;

// ---------------------------------------------------------------------------
// Kernel 0: gate + zero output + zero detect flags
// ---------------------------------------------------------------------------
__global__ void k_prep(const float* __restrict__ Kmat,
                       const float* __restrict__ W,
                       float* __restrict__ out) {
    int i = blockIdx.x * blockDim.x + threadIdx.x;
    if (i == 0) { g_flag_gt1 = 0; g_flag_other = 0; }
    if (i < B*D) {
        int k = i % D;
        g_gate[i] = W[k*D + k] * Kmat[i];
        out[i] = 0.0f;
    }
}

// ---------------------------------------------------------------------------
// Kernel D: classify mask dtype from byte pattern
// ---------------------------------------------------------------------------
__global__ void k_detect_mask(const unsigned char* __restrict__ m) {
    int lgt1 = 0, lother = 0;
    int base = blockIdx.x * 2048;
    for (int j = threadIdx.x; j < 2048; j += 256) {
        int i = base + j;
        unsigned char v = m[i];
        if (v > 1) lgt1 = 1;
        if (v != 0 && (i & 3) != 0) lother = 1;
    }
    if (__syncthreads_or(lgt1))   { if (threadIdx.x == 0) atomicOr(&g_flag_gt1, 1); }
    if (__syncthreads_or(lother)) { if (threadIdx.x == 0) atomicOr(&g_flag_other, 1); }
}

// ---------------------------------------------------------------------------
// Kernel C: w1 [k][n] -> g_w1s, bf16, pre-swizzled SW128 SMEM image.
// One thread per 16-byte output unit (8 consecutive k for one n).
// ---------------------------------------------------------------------------
__global__ void k_cvt_w1(const float* __restrict__ w1) {
    int lin = blockIdx.x * 256 + threadIdx.x;   // 0 .. 32767
    int n     = lin & 511;
    int kq    = (lin >> 9) & 7;
    int chunk = lin >> 12;                      // 0..7
    int k0 = chunk*64 + kq*8;
    __nv_bfloat162 t[4];
    #pragma unroll
    for (int j = 0; j < 4; j++) {
        float f0 = w1[(k0 + 2*j    ) * HID + n];
        float f1 = w1[(k0 + 2*j + 1) * HID + n];
        t[j] = __floats2bfloat162_rn(f0, f1);   // .x = lower k
    }
    uint32_t off = (uint32_t)(n*128 + kq*16);
    *reinterpret_cast<uint4*>(g_w1s + chunk*65536 + SW128(off)) =
        *reinterpret_cast<uint4*>(t);
}

// ---------------------------------------------------------------------------
// Kernel 1: GEMM + fused relu/w2 epilogue -> g_score
//   TC path  : tcgen05 bf16, M=128/CTA, N=512 in TMEM, K in 8 chunks of 64,
//              B via cp.async.bulk from pre-swizzled global, double-buffered.
//   Fallback : f32x2 SGEMM (compute_103 pass).
// ---------------------------------------------------------------------------
#define OFF_TMEM 0
#define MB_BRDY(buf) (8  + (buf)*8)     // B-tile ready (bulk complete_tx)
#define MB_MDONE(buf) (24 + (buf)*8)    // MMA done (buffer free)
#define OFF_BIAS 128                     // 512 f32
#define OFF_W2V  2176                    // 512 f32
#define OFF_GATE 4224                    // 512 f32
#define OFF_A(buf)  (8192  + (buf)*16384)   // 2 x 16 KB (bf16 128x64)
#define OFF_BT(buf) (40960 + (buf)*65536)   // 2 x 64 KB (bf16 512x64)
#define SMEM_BYTES (40960 + 2*65536)        // 172032

__global__ __launch_bounds__(256, 1) void k_gemm_tc(
        const float* __restrict__ V,
        const float* __restrict__ w1,
        const float* __restrict__ b1,
        const float* __restrict__ w2) {
    extern __shared__ char smem[];
    const int tid = threadIdx.x;
    const int row0 = blockIdx.x * 128;
    const int b = row0 >> 11;              // row0 / H

#if TC_OK
    // ======================= tcgen05 bf16 path =======================
    const uint32_t sb = smem_to_u32(smem);
    const int wid = tid >> 5;
    const int lid = tid & 31;

    float* bias = (float*)(smem + OFF_BIAS);
    float* w2s  = (float*)(smem + OFF_W2V);
    float* gs   = (float*)(smem + OFF_GATE);
    for (int i = tid; i < D; i += 256) {
        bias[i] = b1[i];
        w2s[i]  = w2[i];
        gs[i]   = g_gate[b*D + i];
    }
    if (wid == 0) TCGEN05_ALLOC(sb + OFF_TMEM, 512);
    if (tid == 0) {
        MBARRIER_INIT(MB_BRDY(0) + sb, 1);  MBARRIER_INIT(MB_BRDY(1) + sb, 1);
        MBARRIER_INIT(MB_MDONE(0) + sb, 1); MBARRIER_INIT(MB_MDONE(1) + sb, 1);
    }
    __syncthreads();
    uint32_t tmem;
    asm volatile("ld.shared.b32 %0, [%1];" : "=r"(tmem) : "r"(sb + OFF_TMEM));

    const float* Vblk = V + (long long)row0 * D;
    int mdpar[2] = {0, 0};
    int bpar[2]  = {0, 0};

    for (int i = 0; i < 8; i++) {           // 8 K-chunks of 64
        const int buf = i & 1;
        if (i >= 2) {                        // buffer reuse: chunk i-2 MMAs done
            MBARRIER_WAIT_PARITY(sb + MB_MDONE(buf), mdpar[buf]);
            mdpar[buf] ^= 1;
        }
        const int kk = i * 64;

        // B tile: one bulk async copy of the pre-swizzled 64 KB chunk
        if (tid == 0) {
            MBARRIER_EXPECT_TX(sb + MB_BRDY(buf), 65536u);
            CP_ASYNC_BULK(sb + OFF_BT(buf), (const void*)(g_w1s + i*65536), 65536u,
                          sb + MB_BRDY(buf));
        }

        // A tile: 128 rows x 64 bf16 (V * gate), SW128; 4 x 16B per thread
        #pragma unroll
        for (int l = 0; l < 4; l++) {
            int lin = tid + l*256;           // 0..1023
            int m   = lin >> 3;
            int kq  = lin & 7;               // 16B unit (8 bf16) within row
            const float* vp = Vblk + (long long)m*D + kk + kq*8;
            float4 v0 = *reinterpret_cast<const float4*>(vp);
            float4 v1 = *reinterpret_cast<const float4*>(vp + 4);
            const float* gp = gs + kk + kq*8;
            __nv_bfloat162 t[4];
            t[0] = __floats2bfloat162_rn(v0.x*gp[0], v0.y*gp[1]);
            t[1] = __floats2bfloat162_rn(v0.z*gp[2], v0.w*gp[3]);
            t[2] = __floats2bfloat162_rn(v1.x*gp[4], v1.y*gp[5]);
            t[3] = __floats2bfloat162_rn(v1.z*gp[6], v1.w*gp[7]);
            uint32_t off = (uint32_t)(m*128 + kq*16);
            *reinterpret_cast<uint4*>(smem + OFF_A(buf) + SW128(off)) =
                *reinterpret_cast<uint4*>(t);
        }
        FENCE_ASYNC_SHARED();
        __syncthreads();

        if (wid == 0) {
            MBARRIER_WAIT_PARITY(sb + MB_BRDY(buf), bpar[buf]);
            if (elect_one_pred()) {
                uint64_t ad = MAKE_SMEM_DESC(sb + OFF_A(buf));
                uint64_t bd = MAKE_SMEM_DESC(sb + OFF_BT(buf));
                #pragma unroll
                for (int ks = 0; ks < 4; ks++) {           // K=16 per dispatch
                    unsigned en = (i > 0 || ks > 0) ? 1u : 0u;
                    mma_bf16_ss(tmem,       ad + ks*2, bd + ks*2,        IDESC_BF16, en);
                    mma_bf16_ss(tmem + 256, ad + ks*2, bd + 2048 + ks*2, IDESC_BF16, en);
                }
                TCGEN05_COMMIT(sb + MB_MDONE(buf));
            }
        }
        bpar[buf] ^= 1;
    }

    // Drain final MMAs on both buffers
    MBARRIER_WAIT_PARITY(sb + MB_MDONE(0), mdpar[0]);
    MBARRIER_WAIT_PARITY(sb + MB_MDONE(1), mdpar[1]);
    TCGEN05_FENCE_AFTER();

    // Epilogue: lane owns M-row; reduce relu(x+b1)*w2 over all 512 N cols.
    if (wid < 4) {
        float s = 0.0f;
        #pragma unroll 1
        for (int c = 0; c < HID; c += 32) {
            uint32_t r[32];
            TCGEN05_LD_32X32B_X32(r, tmem + c);
            TCGEN05_WAIT_LD();
            #pragma unroll
            for (int j = 0; j < 32; j++) {
                float v = __uint_as_float(r[j]) + bias[c + j];
                s += fmaxf(v, 0.0f) * w2s[c + j];
            }
        }
        TCGEN05_FENCE_BEFORE();
        g_score[row0 + wid*32 + lid] = s;
    }
    __syncthreads();
    if (wid == 0) {
        TCGEN05_RELINQUISH();
        TCGEN05_DEALLOC(tmem, 512);
    }
#else
    // ======================= f32x2 SGEMM fallback =======================
    float* Xs  = (float*)smem;                           // 10240 B
    float* Ws  = (float*)(smem + 128*20*4);              //  8192 B
    float* gsh = (float*)(smem + 128*20*4 + 16*128*4);   //  2048 B
    float* red = gsh + 512;                              //  8704 B
    const int tx = tid & 15;
    const int ty = tid >> 4;

    for (int i = tid; i < D; i += 256) gsh[i] = g_gate[b*D + i];
    __syncthreads();

    float scoreAcc[8];
    #pragma unroll
    for (int i = 0; i < 8; i++) scoreAcc[i] = 0.0f;

    const float* Vblk = V + (long long)row0 * D;

    for (int n0 = 0; n0 < HID; n0 += 128) {
        unsigned long long acc[8][4];
        #pragma unroll
        for (int i = 0; i < 8; i++)
            #pragma unroll
            for (int q = 0; q < 4; q++) acc[i][q] = 0ULL;

        for (int kk = 0; kk < D; kk += 16) {
            #pragma unroll
            for (int l = 0; l < 2; l++) {
                int lin = tid + l*256;
                int m   = lin >> 2;
                int k4  = (lin & 3) << 2;
                float4 v = *reinterpret_cast<const float4*>(
                               &Vblk[(long long)m*D + kk + k4]);
                Xs[m*20 + k4+0] = v.x; Xs[m*20 + k4+1] = v.y;
                Xs[m*20 + k4+2] = v.z; Xs[m*20 + k4+3] = v.w;
            }
            #pragma unroll
            for (int l = 0; l < 2; l++) {
                int lin = tid + l*256;
                int k   = lin >> 5;
                int n4  = (lin & 31) << 2;
                float gk = gsh[kk + k];
                float4 w = *reinterpret_cast<const float4*>(
                               &w1[(long long)(kk+k)*HID + n0 + n4]);
                Ws[k*128 + n4+0] = w.x*gk; Ws[k*128 + n4+1] = w.y*gk;
                Ws[k*128 + n4+2] = w.z*gk; Ws[k*128 + n4+3] = w.w*gk;
            }
            __syncthreads();

            #pragma unroll
            for (int k = 0; k < 16; k++) {
                unsigned long long bvec[4];
                const unsigned long long* wr =
                    reinterpret_cast<const unsigned long long*>(&Ws[k*128 + tx*8]);
                #pragma unroll
                for (int q = 0; q < 4; q++) bvec[q] = wr[q];
                #pragma unroll
                for (int i = 0; i < 8; i++) {
                    float a = Xs[(ty*8 + i)*20 + k];
                    unsigned long long a2;
                    asm("mov.b64 %0, {%1, %1};" : "=l"(a2) : "f"(a));
                    #pragma unroll
                    for (int q = 0; q < 4; q++)
                        asm("fma.rn.f32x2 %0, %1, %2, %0;"
                            : "+l"(acc[i][q]) : "l"(a2), "l"(bvec[q]));
                }
            }
            __syncthreads();
        }

        float b1v[8], w2v[8];
        #pragma unroll
        for (int j = 0; j < 8; j++) {
            b1v[j] = b1[n0 + tx*8 + j];
            w2v[j] = w2[n0 + tx*8 + j];
        }
        #pragma unroll
        for (int i = 0; i < 8; i++) {
            float s = 0.0f;
            #pragma unroll
            for (int q = 0; q < 4; q++) {
                float2 v = *reinterpret_cast<float2*>(&acc[i][q]);
                float c0 = v.x + b1v[q*2+0];
                float c1 = v.y + b1v[q*2+1];
                s += fmaxf(c0, 0.0f) * w2v[q*2+0] + fmaxf(c1, 0.0f) * w2v[q*2+1];
            }
            scoreAcc[i] += s;
        }
    }

    #pragma unroll
    for (int i = 0; i < 8; i++) red[(ty*8 + i)*17 + tx] = scoreAcc[i];
    __syncthreads();
    if (tid < 128) {
        float s = 0.0f;
        #pragma unroll
        for (int t = 0; t < 16; t++) s += red[tid*17 + t];
        g_score[row0 + tid] = s;
    }
#endif
}

// ---------------------------------------------------------------------------
// Kernel 2: masked softmax over h per batch, alpha stored in place
// ---------------------------------------------------------------------------
__global__ __launch_bounds__(256) void k_softmax(const void* __restrict__ mask_raw) {
    const int b   = blockIdx.x;
    const int tid = threadIdx.x;
    __shared__ float sh[256];

    const int mode = g_flag_gt1 ? 2 : (g_flag_other ? 0 : 1);
    const unsigned char* m8  = (const unsigned char*)mask_raw;
    const int*           m32 = (const int*)mask_raw;
    const float*         mf  = (const float*)mask_raw;

    float s[8];
    float mx = -3.0e38f;
    #pragma unroll
    for (int l = 0; l < 8; l++) {
        int idx = b*H + tid + l*256;
        bool masked;
        if (mode == 1)      masked = (m32[idx] != 0);
        else if (mode == 2) masked = (mf[idx] != 0.0f);
        else                masked = (m8[idx] != 0);
        float v = g_score[idx];
        if (masked) v = MASK_FILL_F;
        s[l] = v;
        mx = fmaxf(mx, v);
    }
    sh[tid] = mx; __syncthreads();
    for (int off = 128; off > 0; off >>= 1) {
        if (tid < off) sh[tid] = fmaxf(sh[tid], sh[tid + off]);
        __syncthreads();
    }
    mx = sh[0];
    __syncthreads();

    float e[8], sum = 0.0f;
    #pragma unroll
    for (int l = 0; l < 8; l++) { e[l] = expf(s[l] - mx); sum += e[l]; }
    sh[tid] = sum; __syncthreads();
    for (int off = 128; off > 0; off >>= 1) {
        if (tid < off) sh[tid] += sh[tid + off];
        __syncthreads();
    }
    float inv = 1.0f / sh[0];
    #pragma unroll
    for (int l = 0; l < 8; l++) g_score[b*H + tid + l*256] = e[l] * inv;
}

// ---------------------------------------------------------------------------
// Kernel 3: attn[b,d] = sum_h alpha[b,h] * V[b,h,d]
// ---------------------------------------------------------------------------
__global__ __launch_bounds__(256) void k_wsum(const float* __restrict__ V,
                                              float* __restrict__ out) {
    const int b   = blockIdx.x;
    const int h0  = blockIdx.y * HCHUNK;
    const int tid = threadIdx.x;
    __shared__ float al[HCHUNK];
    al[tid] = g_score[b*H + h0 + tid];
    __syncthreads();

    const float* Vb = V + ((long long)b*H + h0) * D;
    float a0 = 0.0f, a1 = 0.0f;
    #pragma unroll 4
    for (int h = 0; h < HCHUNK; h++) {
        float w = al[h];
        a0 = fmaf(w, Vb[(long long)h*D + tid],       a0);
        a1 = fmaf(w, Vb[(long long)h*D + tid + 256], a1);
    }
    atomicAdd(&out[b*D + tid],       a0);
    atomicAdd(&out[b*D + tid + 256], a1);
}

// ---------------------------------------------------------------------------
extern "C" void kernel_launch(void* const* d_in, const int* in_sizes, int n_in,
                              void* d_out, int out_size) {
    const float* Kmat = (const float*)d_in[0];
    const float* V    = (const float*)d_in[1];
    const void*  mask = d_in[2];
    const float* W    = (const float*)d_in[3];
    const float* w1   = (const float*)d_in[4];
    const float* b1   = (const float*)d_in[5];
    const float* w2   = (const float*)d_in[6];
    // b2 is a uniform score shift -> softmax-invariant, unused.
    float* out = (float*)d_out;

    cudaFuncSetAttribute(k_gemm_tc, cudaFuncAttributeMaxDynamicSharedMemorySize,
                         SMEM_BYTES);

    k_prep<<<(M_TOTAL + 255)/256, 256>>>(Kmat, W, out);
    k_detect_mask<<<64, 256>>>((const unsigned char*)mask);
    k_cvt_w1<<<128, 256>>>(w1);
    k_gemm_tc<<<M_TOTAL/128, 256, SMEM_BYTES>>>(V, w1, b1, w2);
    k_softmax<<<B, 256>>>(mask);
    k_wsum<<<dim3(B, H/HCHUNK), 256>>>(V, out);
}